// round 1
// baseline (speedup 1.0000x reference)
#include <cuda_runtime.h>
#include <cuda_bf16.h>
#include <math.h>
#include <stdint.h>

// ---------------------------------------------------------------------------
// Problem constants
// ---------------------------------------------------------------------------
#define N_IMG   8
#define PER_IM  256
#define NPROP   2048          // N_IMG * PER_IM
#define CCH     256
#define OUTW    7
#define NPTS    49            // 7*7
#define CIN     12544         // 256*49
#define CMID    1024
#define IMTOP   100
#define SCORE_THR 0.05f
#define IOU_THR   0.5f
#define BBOX_CLAMP 4.135166556742356f   // ln(1000/16)

// level tables
__device__ __constant__ int   c_HS[4]   = {160, 80, 40, 20};
__device__ __constant__ int   c_OFFS[4] = {0, 204800, 256000, 268800}; // pixel offsets
__device__ __constant__ float c_STR[4]  = {4.f, 8.f, 16.f, 32.f};

// total pixels across levels*images = 8*(25600+6400+1600+400) = 272000
#define TOTPX 272000

// ---------------------------------------------------------------------------
// Device scratch (static globals; no runtime allocation)
// ---------------------------------------------------------------------------
__device__ float g_pix[TOTPX * CCH];           // NHWC fmaps         (~278.5 MB)
__device__ float g_roi[(size_t)NPROP * CIN];   // roi features (n,p,c) (~102.8 MB)
__device__ float g_w6 [(size_t)CMID * CIN];    // permuted fc6_w (m,p,c) (~51.4 MB)
__device__ float g_h1 [(size_t)NPROP * CMID];
__device__ float g_h2 [(size_t)NPROP * CMID];
__device__ float g_scr[NPROP];
__device__ float g_box[NPROP * 4];

// ---------------------------------------------------------------------------
// Generic 32x32 tiled matrix transpose:  Y[j][i] = X[i][j]
// X is (R x Cc) row-major, Y is (Cc x R) row-major, one matrix per blockIdx.z
// ---------------------------------------------------------------------------
__global__ void ktranspose(const float* __restrict__ in, float* __restrict__ out,
                           int R, int Cc)
{
    __shared__ float tile[32][33];
    size_t mat = blockIdx.z;
    const float* X = in  + mat * (size_t)R * Cc;
    float*       Y = out + mat * (size_t)R * Cc;
    int j0 = blockIdx.x * 32;
    int i0 = blockIdx.y * 32;
    int tx = threadIdx.x, ty = threadIdx.y;   // (32, 8)
#pragma unroll
    for (int u = 0; u < 32; u += 8) {
        int i = i0 + ty + u, j = j0 + tx;
        if (i < R && j < Cc) tile[ty + u][tx] = X[(size_t)i * Cc + j];
    }
    __syncthreads();
#pragma unroll
    for (int u = 0; u < 32; u += 8) {
        int j = j0 + ty + u, i = i0 + tx;
        if (j < Cc && i < R) Y[(size_t)j * R + i] = tile[tx][ty + u];
    }
}

// ---------------------------------------------------------------------------
// ROI align: one block per roi, 256 threads = channels. Reads NHWC g_pix.
// Output layout (n, p, c) so that FC6 weights get permuted to match.
// ---------------------------------------------------------------------------
__global__ void roi_align_kernel(const float* __restrict__ proposals,
                                 const int* __restrict__ imidx,
                                 const float* __restrict__ pix,
                                 float* __restrict__ roi)
{
    int n = blockIdx.x;
    int c = threadIdx.x;

    __shared__ int   s_idx[NPTS][4];
    __shared__ float s_w[NPTS][4];

    float x1 = proposals[n * 4 + 0];
    float y1 = proposals[n * 4 + 1];
    float x2 = proposals[n * 4 + 2];
    float y2 = proposals[n * 4 + 3];

    float area = fmaxf(x2 - x1, 0.f) * fmaxf(y2 - y1, 0.f);
    float lf = floorf(4.0f + log2f(sqrtf(area) / 224.0f + 1e-8f));
    lf = fminf(fmaxf(lf, 2.0f), 5.0f);
    int lvl = (int)lf - 2;

    int   H  = c_HS[lvl];
    int   W  = H;
    float sc = 1.0f / c_STR[lvl];
    int   b  = imidx[n];
    int   basepx = c_OFFS[lvl] + b * H * W;

    if (threadIdx.x < NPTS) {
        int p = threadIdx.x;
        int i = p / 7, j = p % 7;
        float stepx = (x2 - x1) * sc / 7.0f;
        float stepy = (y2 - y1) * sc / 7.0f;
        float gx = x1 * sc + ((float)j + 0.5f) * stepx;
        float gy = y1 * sc + ((float)i + 0.5f) * stepy;
        float x = fminf(fmaxf(gx, 0.f), (float)W - 1.0f);
        float y = fminf(fmaxf(gy, 0.f), (float)H - 1.0f);
        float x0f = floorf(x), y0f = floorf(y);
        int x0i = (int)x0f, y0i = (int)y0f;
        int x1i = min(x0i + 1, W - 1);
        int y1i = min(y0i + 1, H - 1);
        float fx = x - x0f, fy = y - y0f;
        s_idx[p][0] = basepx + y0i * W + x0i;
        s_idx[p][1] = basepx + y0i * W + x1i;
        s_idx[p][2] = basepx + y1i * W + x0i;
        s_idx[p][3] = basepx + y1i * W + x1i;
        s_w[p][0] = (1.f - fy) * (1.f - fx);
        s_w[p][1] = (1.f - fy) * fx;
        s_w[p][2] = fy * (1.f - fx);
        s_w[p][3] = fy * fx;
    }
    __syncthreads();

    float* out = roi + (size_t)n * CIN;
#pragma unroll 1
    for (int p = 0; p < NPTS; p++) {
        float v = s_w[p][0] * pix[(size_t)s_idx[p][0] * CCH + c]
                + s_w[p][1] * pix[(size_t)s_idx[p][1] * CCH + c]
                + s_w[p][2] * pix[(size_t)s_idx[p][2] * CCH + c]
                + s_w[p][3] * pix[(size_t)s_idx[p][3] * CCH + c];
        out[p * CCH + c] = v;
    }
}

// ---------------------------------------------------------------------------
// NT GEMM: C[m][n] = relu( sum_k A[m][k]*B[n][k] + bias[n] )
// A: MxK row-major, B: NxK row-major. 128x128x16 tiles, 256 threads, 8x8/thr.
// Inner product uses packed fma.rn.f32x2 (2x fp32 throughput on sm_103a).
// M, N multiples of 128; K multiple of 16.
// ---------------------------------------------------------------------------
#define GBM 128
#define GBN 128
#define GBK 16

__global__ __launch_bounds__(256, 2)
void gemm_nt(const float* __restrict__ A, const float* __restrict__ B,
             const float* __restrict__ bias, float* __restrict__ C,
             int M, int Nn, int K, int do_relu)
{
    __shared__ float As[2][GBK][GBM];
    __shared__ float Bs[2][GBK][GBN];

    const int tid = threadIdx.x;
    const int tx = tid & 15;
    const int ty = tid >> 4;
    const int r0 = tid >> 1;            // load row within tile (0..127)
    const int kc0 = (tid & 1) * 8;      // base k-column for this thread's 2 float4s

    const float* Ab = A + (size_t)(blockIdx.y * GBM) * K;
    const float* Bb = B + (size_t)(blockIdx.x * GBN) * K;

    unsigned long long acc[4][8];
#pragma unroll
    for (int i = 0; i < 4; i++)
#pragma unroll
        for (int j = 0; j < 8; j++) acc[i][j] = 0ull;

    float4 pa[2], pb[2];
    const int ktiles = K / GBK;

    // prologue: tile 0 -> smem stage 0
#pragma unroll
    for (int q = 0; q < 2; q++) {
        int kc = kc0 + q * 4;
        pa[q] = *(const float4*)(Ab + (size_t)r0 * K + kc);
        pb[q] = *(const float4*)(Bb + (size_t)r0 * K + kc);
    }
#pragma unroll
    for (int q = 0; q < 2; q++) {
        int kc = kc0 + q * 4;
        As[0][kc + 0][r0] = pa[q].x; As[0][kc + 1][r0] = pa[q].y;
        As[0][kc + 2][r0] = pa[q].z; As[0][kc + 3][r0] = pa[q].w;
        Bs[0][kc + 0][r0] = pb[q].x; Bs[0][kc + 1][r0] = pb[q].y;
        Bs[0][kc + 2][r0] = pb[q].z; Bs[0][kc + 3][r0] = pb[q].w;
    }
    __syncthreads();

    int s = 0;
    for (int kt = 0; kt < ktiles; kt++) {
        if (kt + 1 < ktiles) {
            const float* Ap = Ab + (size_t)r0 * K + (size_t)(kt + 1) * GBK;
            const float* Bp = Bb + (size_t)r0 * K + (size_t)(kt + 1) * GBK;
#pragma unroll
            for (int q = 0; q < 2; q++) {
                int kc = kc0 + q * 4;
                pa[q] = *(const float4*)(Ap + kc);
                pb[q] = *(const float4*)(Bp + kc);
            }
        }
#pragma unroll
        for (int kk = 0; kk < GBK; kk++) {
            const unsigned long long* arow =
                (const unsigned long long*)&As[s][kk][ty * 8];
            unsigned long long a2_0 = arow[0], a2_1 = arow[1],
                               a2_2 = arow[2], a2_3 = arow[3];
            const float* brow = &Bs[s][kk][tx * 8];
#pragma unroll
            for (int j = 0; j < 8; j++) {
                float bv = brow[j];
                unsigned long long b2;
                asm("mov.b64 %0, {%1, %1};" : "=l"(b2) : "f"(bv));
                asm("fma.rn.f32x2 %0, %1, %2, %0;" : "+l"(acc[0][j]) : "l"(a2_0), "l"(b2));
                asm("fma.rn.f32x2 %0, %1, %2, %0;" : "+l"(acc[1][j]) : "l"(a2_1), "l"(b2));
                asm("fma.rn.f32x2 %0, %1, %2, %0;" : "+l"(acc[2][j]) : "l"(a2_2), "l"(b2));
                asm("fma.rn.f32x2 %0, %1, %2, %0;" : "+l"(acc[3][j]) : "l"(a2_3), "l"(b2));
            }
        }
        if (kt + 1 < ktiles) {
            int sn = s ^ 1;
#pragma unroll
            for (int q = 0; q < 2; q++) {
                int kc = kc0 + q * 4;
                As[sn][kc + 0][r0] = pa[q].x; As[sn][kc + 1][r0] = pa[q].y;
                As[sn][kc + 2][r0] = pa[q].z; As[sn][kc + 3][r0] = pa[q].w;
                Bs[sn][kc + 0][r0] = pb[q].x; Bs[sn][kc + 1][r0] = pb[q].y;
                Bs[sn][kc + 2][r0] = pb[q].z; Bs[sn][kc + 3][r0] = pb[q].w;
            }
        }
        __syncthreads();
        s ^= 1;
    }

    // epilogue: bias + relu, write two rows per packed accumulator
    int colbase = blockIdx.x * GBN + tx * 8;
    float bj[8];
#pragma unroll
    for (int j = 0; j < 8; j++) bj[j] = bias[colbase + j];

#pragma unroll
    for (int i2 = 0; i2 < 4; i2++) {
        int row0 = blockIdx.y * GBM + ty * 8 + i2 * 2;
        float v0[8], v1[8];
#pragma unroll
        for (int j = 0; j < 8; j++) {
            float lo, hi;
            asm("mov.b64 {%0, %1}, %2;" : "=f"(lo), "=f"(hi) : "l"(acc[i2][j]));
            lo += bj[j]; hi += bj[j];
            if (do_relu) { lo = fmaxf(lo, 0.f); hi = fmaxf(hi, 0.f); }
            v0[j] = lo; v1[j] = hi;
        }
        float* c0 = C + (size_t)row0 * Nn + colbase;
        float* c1 = c0 + Nn;
        *(float4*)(c0)     = make_float4(v0[0], v0[1], v0[2], v0[3]);
        *(float4*)(c0 + 4) = make_float4(v0[4], v0[5], v0[6], v0[7]);
        *(float4*)(c1)     = make_float4(v1[0], v1[1], v1[2], v1[3]);
        *(float4*)(c1 + 4) = make_float4(v1[4], v1[5], v1[6], v1[7]);
    }
}

// ---------------------------------------------------------------------------
// Heads: per proposal (one warp): cls logits (2), reg class-1 (4), softmax,
// box decode + clip + keep mask. Writes g_scr / g_box.
// ---------------------------------------------------------------------------
__global__ void heads_kernel(const float* __restrict__ proposals,
                             const int* __restrict__ imidx,
                             const int* __restrict__ imsizes,
                             const float* __restrict__ cls_w,
                             const float* __restrict__ cls_b,
                             const float* __restrict__ reg_w,
                             const float* __restrict__ reg_b,
                             const float* __restrict__ h2,
                             float* __restrict__ scr_out,
                             float* __restrict__ box_out)
{
    int gt = blockIdx.x * blockDim.x + threadIdx.x;
    int n = gt >> 5;
    int lane = gt & 31;
    if (n >= NPROP) return;

    const float* h = h2 + (size_t)n * CMID;
    float a0 = 0.f, a1 = 0.f, a2 = 0.f, a3 = 0.f, a4 = 0.f, a5 = 0.f;
#pragma unroll 4
    for (int k = lane; k < CMID; k += 32) {
        float hv = h[k];
        a0 += hv * cls_w[k];
        a1 += hv * cls_w[CMID + k];
        a2 += hv * reg_w[4 * CMID + k];
        a3 += hv * reg_w[5 * CMID + k];
        a4 += hv * reg_w[6 * CMID + k];
        a5 += hv * reg_w[7 * CMID + k];
    }
#pragma unroll
    for (int o = 16; o > 0; o >>= 1) {
        a0 += __shfl_down_sync(0xffffffffu, a0, o);
        a1 += __shfl_down_sync(0xffffffffu, a1, o);
        a2 += __shfl_down_sync(0xffffffffu, a2, o);
        a3 += __shfl_down_sync(0xffffffffu, a3, o);
        a4 += __shfl_down_sync(0xffffffffu, a4, o);
        a5 += __shfl_down_sync(0xffffffffu, a5, o);
    }
    if (lane == 0) {
        float l0 = a0 + cls_b[0];
        float l1 = a1 + cls_b[1];
        float m = fmaxf(l0, l1);
        float e0 = expf(l0 - m), e1 = expf(l1 - m);
        float scr = e1 / (e0 + e1);

        float r0 = a2 + reg_b[4];
        float r1 = a3 + reg_b[5];
        float r2 = a4 + reg_b[6];
        float r3 = a5 + reg_b[7];

        float x1 = proposals[n * 4 + 0];
        float y1 = proposals[n * 4 + 1];
        float x2 = proposals[n * 4 + 2];
        float y2 = proposals[n * 4 + 3];
        float w  = x2 - x1, hh = y2 - y1;
        float cx = x1 + 0.5f * w, cy = y1 + 0.5f * hh;
        float dx = r0 / 10.f, dy = r1 / 10.f, dw = r2 / 5.f, dh = r3 / 5.f;
        float pcx = dx * w + cx;
        float pcy = dy * hh + cy;
        float pw = w  * expf(fminf(dw, BBOX_CLAMP));
        float ph = hh * expf(fminf(dh, BBOX_CLAMP));
        int b = imidx[n];
        float szh = (float)imsizes[b * 2 + 0];
        float szw = (float)imsizes[b * 2 + 1];
        float bx1 = fminf(fmaxf(pcx - 0.5f * pw, 0.f), szw);
        float bx2 = fminf(fmaxf(pcx + 0.5f * pw, 0.f), szw);
        float by1 = fminf(fmaxf(pcy - 0.5f * ph, 0.f), szh);
        float by2 = fminf(fmaxf(pcy + 0.5f * ph, 0.f), szh);

        bool keep = (scr > SCORE_THR) && (bx2 - bx1 >= 1.0f) && (by2 - by1 >= 1.0f);
        scr_out[n] = keep ? scr : -1.0f;
        box_out[n * 4 + 0] = bx1;
        box_out[n * 4 + 1] = by1;
        box_out[n * 4 + 2] = bx2;
        box_out[n * 4 + 3] = by2;
    }
}

// ---------------------------------------------------------------------------
// NMS: one block per image, 256 threads. Exact argmax-first-index semantics.
// Output layout in d_out (float32): boxes[0,3200) scr[3200,4000)
// cls[4000,4800) valid[4800,5600)
// ---------------------------------------------------------------------------
__global__ void nms_kernel(const float* __restrict__ scr_in,
                           const float* __restrict__ box_in,
                           float* __restrict__ out)
{
    int img = blockIdx.x;
    int j = threadIdx.x;
    __shared__ float sscr[PER_IM];
    __shared__ float sred[8];
    __shared__ int   sredi[8];
    __shared__ float sbb[4];
    __shared__ int   sbi;
    __shared__ float sbs;

    int gid = img * PER_IM + j;
    float4 box = ((const float4*)box_in)[gid];
    float area = fmaxf(box.z - box.x, 0.f) * fmaxf(box.w - box.y, 0.f);
    sscr[j] = scr_in[gid];
    __syncthreads();

    for (int t = 0; t < IMTOP; t++) {
        // lexicographic argmax: max score, tie -> lowest index
        float v = sscr[j];
        int idx = j;
#pragma unroll
        for (int o = 16; o > 0; o >>= 1) {
            float v2 = __shfl_down_sync(0xffffffffu, v, o);
            int   i2 = __shfl_down_sync(0xffffffffu, idx, o);
            if (v2 > v || (v2 == v && i2 < idx)) { v = v2; idx = i2; }
        }
        if ((j & 31) == 0) { sred[j >> 5] = v; sredi[j >> 5] = idx; }
        __syncthreads();
        if (j == 0) {
            float bv = sred[0]; int bi = sredi[0];
#pragma unroll
            for (int w = 1; w < 8; w++) {
                if (sred[w] > bv || (sred[w] == bv && sredi[w] < bi)) {
                    bv = sred[w]; bi = sredi[w];
                }
            }
            sbi = bi; sbs = bv;
        }
        __syncthreads();
        int bi = sbi; float bs = sbs;
        if (j == bi) {
            sbb[0] = box.x; sbb[1] = box.y; sbb[2] = box.z; sbb[3] = box.w;
            int o = img * IMTOP + t;
            out[o * 4 + 0] = box.x;
            out[o * 4 + 1] = box.y;
            out[o * 4 + 2] = box.z;
            out[o * 4 + 3] = box.w;
            float oscr = fmaxf(bs, -1.0f);
            out[3200 + o] = oscr;
            float val = (bs > SCORE_THR) ? 1.0f : 0.0f;
            out[4000 + o] = val;
            out[4800 + o] = val;
        }
        __syncthreads();
        float xx1 = fmaxf(sbb[0], box.x);
        float yy1 = fmaxf(sbb[1], box.y);
        float xx2 = fminf(sbb[2], box.z);
        float yy2 = fminf(sbb[3], box.w);
        float inter = fmaxf(xx2 - xx1, 0.f) * fmaxf(yy2 - yy1, 0.f);
        float barea = fmaxf(sbb[2] - sbb[0], 0.f) * fmaxf(sbb[3] - sbb[1], 0.f);
        float iou = inter / (barea + area - inter + 1e-6f);
        if (iou > IOU_THR) sscr[j] = -INFINITY;
        if (j == bi) sscr[j] = -INFINITY;
        __syncthreads();
    }
}

// ---------------------------------------------------------------------------
// kernel_launch
// ---------------------------------------------------------------------------
extern "C" void kernel_launch(void* const* d_in, const int* in_sizes, int n_in,
                              void* d_out, int out_size)
{
    const float* proposals = (const float*)d_in[0];
    const int*   imidx     = (const int*)  d_in[1];
    const float* f0        = (const float*)d_in[2];
    const float* f1        = (const float*)d_in[3];
    const float* f2        = (const float*)d_in[4];
    const float* f3        = (const float*)d_in[5];
    const int*   imsizes   = (const int*)  d_in[6];
    const float* fc6_w     = (const float*)d_in[7];
    const float* fc6_b     = (const float*)d_in[8];
    const float* fc7_w     = (const float*)d_in[9];
    const float* fc7_b     = (const float*)d_in[10];
    const float* cls_w     = (const float*)d_in[11];
    const float* cls_b     = (const float*)d_in[12];
    const float* reg_w     = (const float*)d_in[13];
    const float* reg_b     = (const float*)d_in[14];
    float* out = (float*)d_out;

    float *pix, *roi, *w6, *h1, *h2, *scr, *box;
    cudaGetSymbolAddress((void**)&pix, g_pix);
    cudaGetSymbolAddress((void**)&roi, g_roi);
    cudaGetSymbolAddress((void**)&w6,  g_w6);
    cudaGetSymbolAddress((void**)&h1,  g_h1);
    cudaGetSymbolAddress((void**)&h2,  g_h2);
    cudaGetSymbolAddress((void**)&scr, g_scr);
    cudaGetSymbolAddress((void**)&box, g_box);

    dim3 tb(32, 8);
    // NCHW -> NHWC per level (matrix: 256 x P per image)
    ktranspose<<<dim3(800, 8, N_IMG), tb>>>(f0, pix + (size_t)0      * CCH, CCH, 25600);
    ktranspose<<<dim3(200, 8, N_IMG), tb>>>(f1, pix + (size_t)204800 * CCH, CCH, 6400);
    ktranspose<<<dim3(50,  8, N_IMG), tb>>>(f2, pix + (size_t)256000 * CCH, CCH, 1600);
    ktranspose<<<dim3(13,  8, N_IMG), tb>>>(f3, pix + (size_t)268800 * CCH, CCH, 400);
    // fc6_w (m, c*49+p) -> (m, p*256+c): transpose 256x49 per m
    ktranspose<<<dim3(2, 8, CMID), tb>>>(fc6_w, w6, CCH, NPTS);

    roi_align_kernel<<<NPROP, 256>>>(proposals, imidx, pix, roi);

    gemm_nt<<<dim3(CMID / GBN, NPROP / GBM), 256>>>(roi, w6, fc6_b, h1,
                                                    NPROP, CMID, CIN, 1);
    gemm_nt<<<dim3(CMID / GBN, NPROP / GBM), 256>>>(h1, fc7_w, fc7_b, h2,
                                                    NPROP, CMID, CMID, 1);

    heads_kernel<<<NPROP * 32 / 256, 256>>>(proposals, imidx, imsizes,
                                            cls_w, cls_b, reg_w, reg_b,
                                            h2, scr, box);

    nms_kernel<<<N_IMG, PER_IM>>>(scr, box, out);
}